// round 16
// baseline (speedup 1.0000x reference)
#include <cuda_runtime.h>
#include <cuda_bf16.h>
#include <cstdint>

#define E_TOTAL   32768
#define FEAT_DIM  17
#define HID       64
#define R_DIM     768
#define OUT_PER_EDGE 2304
#define LN_EPS    1e-5f

#define EPC       64                  // edges per CTA
#define NCTA      (E_TOTAL / EPC)     // 512
#define KB        128                 // B row: [bhi(64) | blo(64)]
#define CCOLS     48                  // cols per chunk
#define NCH       (R_DIM / CCOLS)     // 16
#define BST2      136                 // smem B row stride (bf16)
#define RBS       68                  // rbuf row stride (floats)
#define SA_ST     68                  // sA row stride (u32): [hi(32)|lo(32)|pad]
#define H_ST      66                  // h row stride (floats)

// main-loop smem byte offsets
#define OFF_SA    0                   // [64][68] u32     17408 B (persistent)
#define OFF_RBUF  17408               // [64][68] f32     17408 B
#define OFF_SBAS  34816               // [64][36] f32      9216 B
#define OFF_SB3   44032               // [768] f32         3072 B
#define OFF_SB0   47104               // [48][136] bf16   13056 B
#define OFF_SB1   60160               // [48][136] bf16   13056 B
#define SM_TOTAL  73216
// prologue aliases: h -> OFF_RBUF ; weights -> OFF_SBAS.. :
#define OFF_PW1   34816
#define OFF_PW2   (OFF_PW1 + FEAT_DIM * HID * 4)   // 39168
#define OFF_PB    (OFF_PW2 + HID * HID * 4)        // 55552: b1|g1|b2|g2

// B: [n][128] bf16 = [bhi(64) | blo(64)]
__device__ __nv_bfloat16 g_bbf[R_DIM * KB];

__device__ __forceinline__ float silu_f(float x) { return x / (1.0f + __expf(-x)); }

__device__ __forceinline__ uint32_t smem_u32(const void* p) {
    uint32_t a;
    asm("{ .reg .u64 t; cvta.to.shared.u64 t, %1; cvt.u32.u64 %0, t; }" : "=r"(a) : "l"(p));
    return a;
}
__device__ __forceinline__ void cp_async16(uint32_t dst, const void* src) {
    asm volatile("cp.async.ca.shared.global [%0], [%1], 16;" :: "r"(dst), "l"(src));
}
#define CP_COMMIT() asm volatile("cp.async.commit_group;" ::: "memory")
#define CP_WAIT0()  asm volatile("cp.async.wait_group 0;" ::: "memory")

__device__ __forceinline__ void mma_bf16(float& d0, float& d1, float& d2, float& d3,
                                         uint32_t a0, uint32_t a1, uint32_t a2, uint32_t a3,
                                         uint32_t b0, uint32_t b1) {
    asm volatile(
        "mma.sync.aligned.m16n8k16.row.col.f32.bf16.bf16.f32 "
        "{%0,%1,%2,%3}, {%4,%5,%6,%7}, {%8,%9}, {%0,%1,%2,%3};"
        : "+f"(d0), "+f"(d1), "+f"(d2), "+f"(d3)
        : "r"(a0), "r"(a1), "r"(a2), "r"(a3), "r"(b0), "r"(b1));
}

// ---------------------------------------------------------------------------
// k0: B prep. g_bbf[n][kk]: kk<64 -> hi(W3[k][n]), else lo residual.
// ---------------------------------------------------------------------------
__global__ __launch_bounds__(256) void k0_prep(const float* __restrict__ W3) {
    int i = blockIdx.x * 256 + threadIdx.x;
    if (i >= R_DIM * KB) return;
    const int n = i >> 7, kk = i & 127;
    const int phase = kk >> 6, k = kk & 63;
    const float wv = W3[k * R_DIM + n];
    const __nv_bfloat16 hi = __float2bfloat16(wv);
    g_bbf[i] = phase ? __float2bfloat16(wv - __bfloat162float(hi)) : hi;
}

// ---------------------------------------------------------------------------
// k2: fused radial-MLP + split-K mma.sync GEMM + tensor product.
// CTA = 64 edges, 256 threads, 8 warps = 4 edge-groups x 2 col-halves.
// A (hi|lo bf16 pairs) lives in smem sA; frags loaded per k-step (frees regs
// for 3 CTAs/SM). Double-buffered cp.async B. Grid = 512 for occupancy.
// ---------------------------------------------------------------------------
__global__ __launch_bounds__(256, 3) void k2_fused(
    const float* __restrict__ feat,
    const float* __restrict__ basis,
    const float* __restrict__ W1, const float* __restrict__ b1, const float* __restrict__ g1,
    const float* __restrict__ W2, const float* __restrict__ b2, const float* __restrict__ g2,
    const float* __restrict__ b3,
    float* __restrict__ out)
{
    extern __shared__ __align__(16) char smem[];
    uint32_t* sA   = (uint32_t*)(smem + OFF_SA);
    float* rbuf = (float*)(smem + OFF_RBUF);
    float* sbas = (float*)(smem + OFF_SBAS);
    float* sb3  = (float*)(smem + OFF_SB3);
    __nv_bfloat16* sB0 = (__nv_bfloat16*)(smem + OFF_SB0);
    __nv_bfloat16* sB1 = (__nv_bfloat16*)(smem + OFF_SB1);
    const uint32_t smb = smem_u32(smem);

    const int t = threadIdx.x;
    const int w = t >> 5, l = t & 31;
    const int g = l >> 2, tig = l & 3;
    const int eg = w & 3, ch2 = w >> 2;       // edge-group, col-half
    const int e0 = blockIdx.x * EPC;

    // ================= prologue: radial MLP, 4 threads per edge ============
    {
        float* sW1p = (float*)(smem + OFF_PW1);
        float* sW2p = (float*)(smem + OFF_PW2);
        float* pb   = (float*)(smem + OFF_PB);   // [b1|g1|b2|g2] x64
        for (int i = t; i < FEAT_DIM * HID; i += 256) sW1p[i] = W1[i];
        for (int i = t; i < HID * HID;     i += 256) sW2p[i] = W2[i];
        if (t < HID) { pb[t] = b1[t]; pb[64 + t] = g1[t]; pb[128 + t] = b2[t]; pb[192 + t] = g2[t]; }
        __syncthreads();

        const int eL = t >> 2, q = t & 3, jb = 16 * q;
        const float* fr = feat + (size_t)(e0 + eL) * FEAT_DIM;
        float* hrow = rbuf + eL * H_ST;          // h aliases rbuf region

        float x[16];
#pragma unroll
        for (int jj = 0; jj < 16; jj++) x[jj] = pb[jb + jj];
#pragma unroll 1
        for (int c = 0; c < FEAT_DIM; c++) {
            const float fv = fr[c];
            const float4* w4 = (const float4*)(sW1p + c * HID + jb);
#pragma unroll
            for (int j4 = 0; j4 < 4; j4++) {
                float4 wv = w4[j4];
                x[4*j4+0] = fmaf(fv, wv.x, x[4*j4+0]);
                x[4*j4+1] = fmaf(fv, wv.y, x[4*j4+1]);
                x[4*j4+2] = fmaf(fv, wv.z, x[4*j4+2]);
                x[4*j4+3] = fmaf(fv, wv.w, x[4*j4+3]);
            }
        }
        {
            float s = 0.f, qq = 0.f;
#pragma unroll
            for (int jj = 0; jj < 16; jj++) { x[jj] = silu_f(x[jj]); s += x[jj]; qq += x[jj]*x[jj]; }
            s += __shfl_xor_sync(0xffffffffu, s, 1);
            qq += __shfl_xor_sync(0xffffffffu, qq, 1);
            s += __shfl_xor_sync(0xffffffffu, s, 2);
            qq += __shfl_xor_sync(0xffffffffu, qq, 2);
            const float mu = s * (1.0f/64.0f);
            const float var = qq * (1.0f/64.0f) - mu*mu;
            const float rs = rsqrtf(var + LN_EPS);
#pragma unroll
            for (int jj = 0; jj < 16; jj++)
                hrow[jb + jj] = (x[jj] - mu) * rs * pb[64 + jb + jj];
        }
        __syncwarp();

        // layer 2
#pragma unroll
        for (int jj = 0; jj < 16; jj++) x[jj] = pb[128 + jb + jj];
#pragma unroll 1
        for (int k = 0; k < HID; k++) {
            const float hv = hrow[k];
            const float4* w4 = (const float4*)(sW2p + k * HID + jb);
#pragma unroll
            for (int j4 = 0; j4 < 4; j4++) {
                float4 wv = w4[j4];
                x[4*j4+0] = fmaf(hv, wv.x, x[4*j4+0]);
                x[4*j4+1] = fmaf(hv, wv.y, x[4*j4+1]);
                x[4*j4+2] = fmaf(hv, wv.z, x[4*j4+2]);
                x[4*j4+3] = fmaf(hv, wv.w, x[4*j4+3]);
            }
        }
        float s = 0.f, qq = 0.f;
#pragma unroll
        for (int jj = 0; jj < 16; jj++) { x[jj] = silu_f(x[jj]); s += x[jj]; qq += x[jj]*x[jj]; }
        s += __shfl_xor_sync(0xffffffffu, s, 1);
        qq += __shfl_xor_sync(0xffffffffu, qq, 1);
        s += __shfl_xor_sync(0xffffffffu, s, 2);
        qq += __shfl_xor_sync(0xffffffffu, qq, 2);
        const float mu = s * (1.0f/64.0f);
        const float var = qq * (1.0f/64.0f) - mu*mu;
        const float rs = rsqrtf(var + LN_EPS);

        // pack hi/lo bf16 pairs straight into sA [hi(32)|lo(32)]
        uint32_t* row = sA + eL * SA_ST;
#pragma unroll
        for (int p = 0; p < 8; p++) {
            const float h0 = (x[2*p]   - mu) * rs * pb[192 + jb + 2*p];
            const float h1 = (x[2*p+1] - mu) * rs * pb[192 + jb + 2*p+1];
            const __nv_bfloat16 a0 = __float2bfloat16(h0), a1 = __float2bfloat16(h1);
            const __nv_bfloat16 c0 = __float2bfloat16(h0 - __bfloat162float(a0));
            const __nv_bfloat16 c1 = __float2bfloat16(h1 - __bfloat162float(a1));
            row[8*q + p]      = (uint32_t)__bfloat16_as_ushort(a0) | ((uint32_t)__bfloat16_as_ushort(a1) << 16);
            row[32 + 8*q + p] = (uint32_t)__bfloat16_as_ushort(c0) | ((uint32_t)__bfloat16_as_ushort(c1) << 16);
        }
    }
    __syncthreads();

    // stage basis + b3 + B chunk 0 (cp.async)
    for (int i = t; i < EPC * 27; i += 256) {
        const int e = i / 27, r = i - 27 * e;
        const int dd = r / 9, rr = r - 9 * dd;
        sbas[e * 36 + dd * 12 + rr] = basis[(size_t)(e0 + e) * 27 + r];
    }
    for (int i = t; i < R_DIM; i += 256) sb3[i] = b3[i];
    {
        const int row = t >> 2, qq4 = (t & 3) << 2;   // 64 rows? no: 256 thr -> rows 0..63, 4 quads
        // 48 rows x 16 quads = 768 cp.async; thread does 3
#pragma unroll
        for (int r3 = 0; r3 < 3; r3++) {
            const int i = r3 * 256 + t;
            const int rw = i >> 4, qq = i & 15;
            cp_async16(smb + OFF_SB0 + rw * (BST2 * 2) + qq * 16,
                       g_bbf + (size_t)rw * KB + qq * 8);
        }
    }
    CP_COMMIT();
    CP_WAIT0();
    __syncthreads();

    // per-thread constants
    const int e_base = t / 36;
    const int rem_base = t - 36 * e_base;
    const int eL0 = 16 * eg + g;
    const uint32_t* arow0 = sA + eL0 * SA_ST + tig;        // + kb*8 (+4)
    const uint32_t* arow1 = sA + (eL0 + 8) * SA_ST + tig;
    // GEMM write-back column constants (3 tiles in this col-half)
    int cc_t[3], a0_t[3], a1_t[3];
#pragma unroll
    for (int tt = 0; tt < 3; tt++) {
        const int cc0 = 24 * ch2 + 8 * tt + 2 * tig;
        cc_t[tt] = cc0;
        a0_t[tt] = (cc0 / 3) * 4 + (cc0 % 3);
        a1_t[tt] = ((cc0 + 1) / 3) * 4 + ((cc0 + 1) % 3);
    }

    // ================= main loop: 16 chunks ================================
#pragma unroll 1
    for (int c = 0; c < NCH; c++) {
        const __nv_bfloat16* sBc = (c & 1) ? sB1 : sB0;
        const uint32_t sBn_u = smb + ((c & 1) ? OFF_SB0 : OFF_SB1);

        // ---- GEMM: 3 n-tiles (this warp's 24 cols), A frags from smem ----
        {
            const __nv_bfloat16* brA = sBc + (24 * ch2 + g) * BST2;
            const __nv_bfloat16* brB = brA + 8 * BST2;
            const __nv_bfloat16* brC = brB + 8 * BST2;
            float dA0=0.f,dA1=0.f,dA2=0.f,dA3=0.f;
            float dB0=0.f,dB1=0.f,dB2=0.f,dB3=0.f;
            float dC0=0.f,dC1=0.f,dC2=0.f,dC3=0.f;
#pragma unroll
            for (int kb = 0; kb < 4; kb++) {
                const int ko = kb * 8;
                const uint32_t ah0 = arow0[ko], ah1 = arow1[ko];
                const uint32_t ah2 = arow0[ko + 4], ah3 = arow1[ko + 4];
                const uint32_t al0 = arow0[32 + ko], al1 = arow1[32 + ko];
                const uint32_t al2 = arow0[32 + ko + 4], al3 = arow1[32 + ko + 4];
                const int keh = kb * 16 + 2 * tig;
                const int kel = keh + 64;
                // tile A
                {
                    const uint32_t bh0 = *(const uint32_t*)(brA + keh);
                    const uint32_t bh1 = *(const uint32_t*)(brA + keh + 8);
                    const uint32_t bl0 = *(const uint32_t*)(brA + kel);
                    const uint32_t bl1 = *(const uint32_t*)(brA + kel + 8);
                    mma_bf16(dA0,dA1,dA2,dA3, ah0,ah1,ah2,ah3, bh0,bh1);
                    mma_bf16(dA0,dA1,dA2,dA3, al0,al1,al2,al3, bh0,bh1);
                    mma_bf16(dA0,dA1,dA2,dA3, ah0,ah1,ah2,ah3, bl0,bl1);
                }
                // tile B
                {
                    const uint32_t bh0 = *(const uint32_t*)(brB + keh);
                    const uint32_t bh1 = *(const uint32_t*)(brB + keh + 8);
                    const uint32_t bl0 = *(const uint32_t*)(brB + kel);
                    const uint32_t bl1 = *(const uint32_t*)(brB + kel + 8);
                    mma_bf16(dB0,dB1,dB2,dB3, ah0,ah1,ah2,ah3, bh0,bh1);
                    mma_bf16(dB0,dB1,dB2,dB3, al0,al1,al2,al3, bh0,bh1);
                    mma_bf16(dB0,dB1,dB2,dB3, ah0,ah1,ah2,ah3, bl0,bl1);
                }
                // tile C
                {
                    const uint32_t bh0 = *(const uint32_t*)(brC + keh);
                    const uint32_t bh1 = *(const uint32_t*)(brC + keh + 8);
                    const uint32_t bl0 = *(const uint32_t*)(brC + kel);
                    const uint32_t bl1 = *(const uint32_t*)(brC + kel + 8);
                    mma_bf16(dC0,dC1,dC2,dC3, ah0,ah1,ah2,ah3, bh0,bh1);
                    mma_bf16(dC0,dC1,dC2,dC3, al0,al1,al2,al3, bh0,bh1);
                    mma_bf16(dC0,dC1,dC2,dC3, ah0,ah1,ah2,ah3, bl0,bl1);
                }
            }
            // bias + write rbuf triples
#pragma unroll
            for (int tt = 0; tt < 3; tt++) {
                float v0, v1, v2, v3;
                if (tt == 0)      { v0=dA0; v1=dA1; v2=dA2; v3=dA3; }
                else if (tt == 1) { v0=dB0; v1=dB1; v2=dB2; v3=dB3; }
                else              { v0=dC0; v1=dC1; v2=dC2; v3=dC3; }
                const float bs0 = sb3[c * CCOLS + cc_t[tt]];
                const float bs1 = sb3[c * CCOLS + cc_t[tt] + 1];
                rbuf[eL0 * RBS + a0_t[tt]]       = v0 + bs0;
                rbuf[eL0 * RBS + a1_t[tt]]       = v1 + bs1;
                rbuf[(eL0 + 8) * RBS + a0_t[tt]] = v2 + bs0;
                rbuf[(eL0 + 8) * RBS + a1_t[tt]] = v3 + bs1;
            }
        }
        __syncthreads();   // rbuf ready; other sB buffer free

        // ---- prefetch next B chunk into the other buffer (lands during TP)
        if (c + 1 < NCH) {
#pragma unroll
            for (int r3 = 0; r3 < 3; r3++) {
                const int i = r3 * 256 + t;
                const int rw = i >> 4, qq = i & 15;
                cp_async16(sBn_u + rw * (BST2 * 2) + qq * 16,
                           g_bbf + (size_t)((c + 1) * CCOLS + rw) * KB + qq * 8);
            }
            CP_COMMIT();
        }

        // ---- TP phase: 64 edges x 144 floats (o = c) = 2304 float4 ----
        {
            int e = e_base, rem = rem_base;
#pragma unroll
            for (int it = 0; it < 9; it++) {
                const int dd = (rem >= 24) ? 2 : ((rem >= 12) ? 1 : 0);
                const int pos = rem - 12 * dd;
                const int p3 = (pos * 11) >> 5;
                const int i0 = pos + p3;
                const int m0 = pos - 3 * p3;
                const int s4 = 4 * pos;
                const float* rrow = rbuf + e * RBS + i0 * 4;
                const float4 ra  = *(const float4*)(rrow);
                const float4 rbt = *(const float4*)(rrow + 4);
                const float* B = sbas + e * 36 + dd * 12;
                const float4 b04 = *(const float4*)(B);
                const float4 b14 = *(const float4*)(B + 4);
                const float  b8  = B[8];
                const float da0 = ra.x * b04.x + ra.y * b04.y + ra.z * b04.z;
                const float da1 = ra.x * b04.w + ra.y * b14.x + ra.z * b14.y;
                const float da2 = ra.x * b14.z + ra.y * b14.w + ra.z * b8;
                const float db0 = rbt.x * b04.x + rbt.y * b04.y + rbt.z * b04.z;
                const float db1 = rbt.x * b04.w + rbt.y * b14.x + rbt.z * b14.y;
                const float db2 = rbt.x * b14.z + rbt.y * b14.w + rbt.z * b8;
                float4 ov;
                ov.x = (m0 == 0) ? da0 : ((m0 == 1) ? da1 : da2);
                ov.y = (m0 == 0) ? da1 : ((m0 == 1) ? da2 : db0);
                ov.z = (m0 == 0) ? da2 : ((m0 == 1) ? db0 : db1);
                ov.w = (m0 == 0) ? db0 : ((m0 == 1) ? db1 : db2);
                *(float4*)(out + (size_t)(e0 + e) * OUT_PER_EDGE + c * 144 + dd * 48 + s4) = ov;
                e += 7; rem += 4;
                if (rem >= 36) { rem -= 36; e += 1; }
            }
        }
        CP_WAIT0();
        __syncthreads();   // next sB visible; rbuf free
    }
}

// ---------------------------------------------------------------------------
extern "C" void kernel_launch(void* const* d_in, const int* in_sizes, int n_in,
                              void* d_out, int out_size)
{
    const float* feat  = (const float*)d_in[0];
    const float* basis = (const float*)d_in[1];
    const float* W1    = (const float*)d_in[2];
    const float* b1    = (const float*)d_in[3];
    const float* g1    = (const float*)d_in[4];
    const float* W2    = (const float*)d_in[5];
    const float* b2    = (const float*)d_in[6];
    const float* g2    = (const float*)d_in[7];
    const float* W3    = (const float*)d_in[8];
    const float* b3    = (const float*)d_in[9];
    float* out = (float*)d_out;

    cudaFuncSetAttribute(k2_fused, cudaFuncAttributeMaxDynamicSharedMemorySize, SM_TOTAL);

    k0_prep<<<(R_DIM * KB + 255) / 256, 256>>>(W3);
    k2_fused<<<NCTA, 256, SM_TOTAL>>>(feat, basis, W1, b1, g1, W2, b2, g2, b3, out);
}

// round 17
// speedup vs baseline: 1.3201x; 1.3201x over previous
#include <cuda_runtime.h>
#include <cuda_bf16.h>
#include <cstdint>

#define E_TOTAL   32768
#define FEAT_DIM  17
#define HID       64
#define R_DIM     768
#define OUT_PER_EDGE 2304
#define LN_EPS    1e-5f

#define EPC       128                 // edges per CTA
#define NCTA      (E_TOTAL / EPC)     // 256
#define KB        128                 // B row: [bhi(64) | blo(64)]
#define CCOLS     48                  // cols per chunk
#define NCH       (R_DIM / CCOLS)     // 16
#define BST2      136                 // smem B row stride (bf16)
#define RBS       68                  // rbuf row stride (floats)
#define SA_ST     68                  // sA row stride (u32): [hi(32)|lo(32)|pad]
#define H_ST      66                  // h row stride (floats)

// main-loop smem byte offsets
#define OFF_RBUF  0                   // [128][68] f32   34816 B (sA alias in prologue)
#define OFF_SBAS  34816               // [128][40] f32   20480 B
#define OFF_SB3   55296               // [768] f32        3072 B
#define OFF_SB0   58368               // [48][136] bf16  13056 B
#define OFF_SB1   71424               // [48][136] bf16  13056 B
#define SM_TOTAL  84480
// prologue weight aliases (region reused by sbas/sb3 afterwards)
#define OFF_PW1   34816
#define OFF_PW2   (OFF_PW1 + FEAT_DIM * HID * 4)   // 39168
#define OFF_PB    (OFF_PW2 + HID * HID * 4)        // 55552

// B: [n][128] bf16 = [bhi(64) | blo(64)]
__device__ __nv_bfloat16 g_bbf[R_DIM * KB];

__device__ __forceinline__ float silu_f(float x) { return x / (1.0f + __expf(-x)); }

__device__ __forceinline__ uint32_t smem_u32(const void* p) {
    uint32_t a;
    asm("{ .reg .u64 t; cvta.to.shared.u64 t, %1; cvt.u32.u64 %0, t; }" : "=r"(a) : "l"(p));
    return a;
}
__device__ __forceinline__ void cp_async16(uint32_t dst, const void* src) {
    asm volatile("cp.async.ca.shared.global [%0], [%1], 16;" :: "r"(dst), "l"(src));
}
#define CP_COMMIT() asm volatile("cp.async.commit_group;" ::: "memory")
#define CP_WAIT0()  asm volatile("cp.async.wait_group 0;" ::: "memory")

__device__ __forceinline__ void mma_bf16(float& d0, float& d1, float& d2, float& d3,
                                         uint32_t a0, uint32_t a1, uint32_t a2, uint32_t a3,
                                         uint32_t b0, uint32_t b1) {
    asm volatile(
        "mma.sync.aligned.m16n8k16.row.col.f32.bf16.bf16.f32 "
        "{%0,%1,%2,%3}, {%4,%5,%6,%7}, {%8,%9}, {%0,%1,%2,%3};"
        : "+f"(d0), "+f"(d1), "+f"(d2), "+f"(d3)
        : "r"(a0), "r"(a1), "r"(a2), "r"(a3), "r"(b0), "r"(b1));
}

// ---------------------------------------------------------------------------
// k0: B prep. g_bbf[n][kk]: kk<64 -> hi(W3[k][n]), else lo residual.
// ---------------------------------------------------------------------------
__global__ __launch_bounds__(256) void k0_prep(const float* __restrict__ W3) {
    int i = blockIdx.x * 256 + threadIdx.x;
    if (i >= R_DIM * KB) return;
    const int n = i >> 7, kk = i & 127;
    const int phase = kk >> 6, k = kk & 63;
    const float wv = W3[k * R_DIM + n];
    const __nv_bfloat16 hi = __float2bfloat16(wv);
    g_bbf[i] = phase ? __float2bfloat16(wv - __bfloat162float(hi)) : hi;
}

// ---------------------------------------------------------------------------
// k2: fused radial-MLP + split-K mma.sync GEMM + WARP-LOCAL tensor product.
// CTA = 128 edges, 8 warps. Warp w owns edges [16w,16w+16) end-to-end:
// GEMM writes warp-private rbuf rows, __syncwarp, TP+store of the same rows.
// One __syncthreads per chunk (B double-buffer flip). A frags in registers.
// ---------------------------------------------------------------------------
__global__ __launch_bounds__(256, 2) void k2_fused(
    const float* __restrict__ feat,
    const float* __restrict__ basis,
    const float* __restrict__ W1, const float* __restrict__ b1, const float* __restrict__ g1,
    const float* __restrict__ W2, const float* __restrict__ b2, const float* __restrict__ g2,
    const float* __restrict__ b3,
    float* __restrict__ out)
{
    extern __shared__ __align__(16) char smem[];
    float* rbuf = (float*)(smem + OFF_RBUF);
    float* sbas = (float*)(smem + OFF_SBAS);
    float* sb3  = (float*)(smem + OFF_SB3);
    __nv_bfloat16* sB0 = (__nv_bfloat16*)(smem + OFF_SB0);
    __nv_bfloat16* sB1 = (__nv_bfloat16*)(smem + OFF_SB1);
    const uint32_t smb = smem_u32(smem);

    const int t = threadIdx.x;
    const int w = t >> 5, l = t & 31;
    const int g = l >> 2, tig = l & 3;
    const int e0 = blockIdx.x * EPC;

    // ================= prologue: radial MLP, 2 threads per edge ============
    {
        float* sW1p = (float*)(smem + OFF_PW1);
        float* sW2p = (float*)(smem + OFF_PW2);
        float* pb   = (float*)(smem + OFF_PB);   // [b1|g1|b2|g2] x64
        for (int i = t; i < FEAT_DIM * HID; i += 256) sW1p[i] = W1[i];
        for (int i = t; i < HID * HID;     i += 256) sW2p[i] = W2[i];
        if (t < HID) { pb[t] = b1[t]; pb[64 + t] = g1[t]; pb[128 + t] = b2[t]; pb[192 + t] = g2[t]; }
        __syncthreads();

        const int eL = t >> 1, half = t & 1, jb = 32 * half;
        const float* fr = feat + (size_t)(e0 + eL) * FEAT_DIM;
        float* hrow = (float*)smem + eL * H_ST;   // aliases rbuf region

        float x[32];
#pragma unroll
        for (int jj = 0; jj < 32; jj++) x[jj] = pb[jb + jj];
#pragma unroll 1
        for (int c = 0; c < FEAT_DIM; c++) {
            const float fv = fr[c];
            const float4* w4 = (const float4*)(sW1p + c * HID + jb);
#pragma unroll
            for (int j4 = 0; j4 < 8; j4++) {
                float4 wv = w4[j4];
                x[4*j4+0] = fmaf(fv, wv.x, x[4*j4+0]);
                x[4*j4+1] = fmaf(fv, wv.y, x[4*j4+1]);
                x[4*j4+2] = fmaf(fv, wv.z, x[4*j4+2]);
                x[4*j4+3] = fmaf(fv, wv.w, x[4*j4+3]);
            }
        }
        {
            float s = 0.f, q = 0.f;
#pragma unroll
            for (int jj = 0; jj < 32; jj++) { x[jj] = silu_f(x[jj]); s += x[jj]; q += x[jj]*x[jj]; }
            s += __shfl_xor_sync(0xffffffffu, s, 1);
            q += __shfl_xor_sync(0xffffffffu, q, 1);
            const float mu = s * (1.0f/64.0f);
            const float var = q * (1.0f/64.0f) - mu*mu;
            const float rs = rsqrtf(var + LN_EPS);
#pragma unroll
            for (int jj = 0; jj < 32; jj++)
                hrow[jb + jj] = (x[jj] - mu) * rs * pb[64 + jb + jj];
        }
        __syncwarp();

        // layer 2
#pragma unroll
        for (int jj = 0; jj < 32; jj++) x[jj] = pb[128 + jb + jj];
#pragma unroll 1
        for (int k = 0; k < HID; k++) {
            const float hv = hrow[k];
            const float4* w4 = (const float4*)(sW2p + k * HID + jb);
#pragma unroll
            for (int j4 = 0; j4 < 8; j4++) {
                float4 wv = w4[j4];
                x[4*j4+0] = fmaf(hv, wv.x, x[4*j4+0]);
                x[4*j4+1] = fmaf(hv, wv.y, x[4*j4+1]);
                x[4*j4+2] = fmaf(hv, wv.z, x[4*j4+2]);
                x[4*j4+3] = fmaf(hv, wv.w, x[4*j4+3]);
            }
        }
        float s = 0.f, q = 0.f;
#pragma unroll
        for (int jj = 0; jj < 32; jj++) { x[jj] = silu_f(x[jj]); s += x[jj]; q += x[jj]*x[jj]; }
        s += __shfl_xor_sync(0xffffffffu, s, 1);
        q += __shfl_xor_sync(0xffffffffu, q, 1);
        const float mu = s * (1.0f/64.0f);
        const float var = q * (1.0f/64.0f) - mu*mu;
        const float rs = rsqrtf(var + LN_EPS);

        uint32_t hi16[16], lo16[16];
#pragma unroll
        for (int p = 0; p < 16; p++) {
            const float h0 = (x[2*p]   - mu) * rs * pb[192 + jb + 2*p];
            const float h1 = (x[2*p+1] - mu) * rs * pb[192 + jb + 2*p+1];
            const __nv_bfloat16 a0 = __float2bfloat16(h0), a1 = __float2bfloat16(h1);
            const __nv_bfloat16 c0 = __float2bfloat16(h0 - __bfloat162float(a0));
            const __nv_bfloat16 c1 = __float2bfloat16(h1 - __bfloat162float(a1));
            hi16[p] = (uint32_t)__bfloat16_as_ushort(a0) | ((uint32_t)__bfloat16_as_ushort(a1) << 16);
            lo16[p] = (uint32_t)__bfloat16_as_ushort(c0) | ((uint32_t)__bfloat16_as_ushort(c1) << 16);
        }
        __syncthreads();   // hrow/sW2p reads done before sA overwrite

        uint32_t* row = (uint32_t*)smem + eL * SA_ST;   // sA aliases rbuf
#pragma unroll
        for (int p = 0; p < 16; p++) row[16 * half + p] = hi16[p];
#pragma unroll
        for (int p = 0; p < 16; p++) row[32 + 16 * half + p] = lo16[p];
    }
    __syncthreads();

    // A fragments: 8 distinct (hi 0-3, lo 4-7), conflict-free LDS
    uint32_t af[8][4];
    {
        const uint32_t* sA = (const uint32_t*)smem;
        const int r0 = (16 * w + g) * SA_ST;
        const int r1 = (16 * w + g + 8) * SA_ST;
#pragma unroll
        for (int kf = 0; kf < 8; kf++) {
            const int ko = kf * 8 + tig;
            af[kf][0] = sA[r0 + ko];
            af[kf][1] = sA[r1 + ko];
            af[kf][2] = sA[r0 + ko + 4];
            af[kf][3] = sA[r1 + ko + 4];
        }
    }
    __syncthreads();   // sA reads done; rbuf region free

    // stage basis + b3 + B chunk 0
    for (int i = t; i < EPC * 27; i += 256) {
        const int e = i / 27, r = i - 27 * e;
        const int dd = r / 9, rr = r - 9 * dd;
        sbas[e * 40 + dd * 12 + rr] = basis[(size_t)(e0 + e) * 27 + r];
    }
    for (int i = t; i < R_DIM; i += 256) sb3[i] = b3[i];
#pragma unroll
    for (int r3 = 0; r3 < 3; r3++) {
        const int i = r3 * 256 + t;
        const int rw = i >> 4, qq = i & 15;
        cp_async16(smb + OFF_SB0 + rw * (BST2 * 2) + qq * 16,
                   g_bbf + (size_t)rw * KB + qq * 8);
    }
    CP_COMMIT();
    CP_WAIT0();
    __syncthreads();

    // precomputed write-back index tables (6 column-pairs per thread)
    int a0_t[6], a1_t[6], cc_t[6];
#pragma unroll
    for (int jtt = 0; jtt < 6; jtt++) {
        const int cc0 = jtt * 8 + 2 * tig;
        cc_t[jtt] = cc0;
        a0_t[jtt] = (cc0 / 3) * 4 + (cc0 % 3);
        a1_t[jtt] = ((cc0 + 1) / 3) * 4 + ((cc0 + 1) % 3);
    }
    const int eL0 = 16 * w + g;
    float* obase = out + (size_t)(e0 + 16 * w) * OUT_PER_EDGE;
    float* rwarp = rbuf + 16 * w * RBS;
    const float* bwarp = sbas + 16 * w * 40;

    // ================= main loop: 16 chunks, ONE CTA barrier each ==========
#pragma unroll 1
    for (int c = 0; c < NCH; c++) {
        const __nv_bfloat16* sBc = (c & 1) ? sB1 : sB0;
        const uint32_t sBn_u = smb + ((c & 1) ? OFF_SB0 : OFF_SB1);

        // ---- GEMM: 6 n-tiles (2 at a time), 3-term split with bhi reuse ----
#pragma unroll 1
        for (int j = 0; j < 6; j += 2) {
            const __nv_bfloat16* br0 = sBc + (j * 8 + g) * BST2;
            const __nv_bfloat16* br1 = br0 + 8 * BST2;
            float d0 = 0.f, d1 = 0.f, d2 = 0.f, d3 = 0.f;
            float f0 = 0.f, f1 = 0.f, f2 = 0.f, f3 = 0.f;
#pragma unroll
            for (int kb = 0; kb < 4; kb++) {
                const int keh = kb * 16 + 2 * tig;
                const int kel = keh + 64;
                const uint32_t b00 = *(const uint32_t*)(br0 + keh);
                const uint32_t b01 = *(const uint32_t*)(br0 + keh + 8);
                const uint32_t b10 = *(const uint32_t*)(br1 + keh);
                const uint32_t b11 = *(const uint32_t*)(br1 + keh + 8);
                mma_bf16(d0,d1,d2,d3, af[kb][0],af[kb][1],af[kb][2],af[kb][3], b00,b01);
                mma_bf16(f0,f1,f2,f3, af[kb][0],af[kb][1],af[kb][2],af[kb][3], b10,b11);
                mma_bf16(d0,d1,d2,d3, af[kb+4][0],af[kb+4][1],af[kb+4][2],af[kb+4][3], b00,b01);
                mma_bf16(f0,f1,f2,f3, af[kb+4][0],af[kb+4][1],af[kb+4][2],af[kb+4][3], b10,b11);
                const uint32_t c00 = *(const uint32_t*)(br0 + kel);
                const uint32_t c01 = *(const uint32_t*)(br0 + kel + 8);
                const uint32_t c10 = *(const uint32_t*)(br1 + kel);
                const uint32_t c11 = *(const uint32_t*)(br1 + kel + 8);
                mma_bf16(d0,d1,d2,d3, af[kb][0],af[kb][1],af[kb][2],af[kb][3], c00,c01);
                mma_bf16(f0,f1,f2,f3, af[kb][0],af[kb][1],af[kb][2],af[kb][3], c10,c11);
            }
#pragma unroll
            for (int tt = 0; tt < 2; tt++) {
                const int jtt = j + tt;
                const float bs0 = sb3[c * CCOLS + cc_t[jtt]];
                const float bs1 = sb3[c * CCOLS + cc_t[jtt] + 1];
                rbuf[eL0 * RBS + a0_t[jtt]]       = (tt ? f0 : d0) + bs0;
                rbuf[eL0 * RBS + a1_t[jtt]]       = (tt ? f1 : d1) + bs1;
                rbuf[(eL0 + 8) * RBS + a0_t[jtt]] = (tt ? f2 : d2) + bs0;
                rbuf[(eL0 + 8) * RBS + a1_t[jtt]] = (tt ? f3 : d3) + bs1;
            }
        }
        __syncwarp();      // warp-local rbuf ready

        // ---- prefetch next B chunk into the other buffer ----
        if (c + 1 < NCH) {
#pragma unroll
            for (int r3 = 0; r3 < 3; r3++) {
                const int i = r3 * 256 + t;
                const int rw = i >> 4, qq = i & 15;
                cp_async16(sBn_u + rw * (BST2 * 2) + qq * 16,
                           g_bbf + (size_t)((c + 1) * CCOLS + rw) * KB + qq * 8);
            }
            CP_COMMIT();
        }

        // ---- WARP-LOCAL TP: this warp's 16 edges x 144 floats = 576 f4 ----
        {
            float* oc = obase + c * 144;
            int e = 0, rem = l;
#pragma unroll
            for (int it = 0; it < 18; it++) {
                const int dd = (rem >= 24) ? 2 : ((rem >= 12) ? 1 : 0);
                const int pos = rem - 12 * dd;
                const int p3 = (pos * 11) >> 5;
                const int i0 = pos + p3;
                const int m0 = pos - 3 * p3;
                const float* rrow = rwarp + e * RBS + i0 * 4;
                const float4 ra  = *(const float4*)(rrow);
                const float4 rbt = *(const float4*)(rrow + 4);
                const float* B = bwarp + e * 40 + dd * 12;
                const float4 b04 = *(const float4*)(B);
                const float4 b14 = *(const float4*)(B + 4);
                const float  b8  = B[8];
                const float da0 = ra.x * b04.x + ra.y * b04.y + ra.z * b04.z;
                const float da1 = ra.x * b04.w + ra.y * b14.x + ra.z * b14.y;
                const float da2 = ra.x * b14.z + ra.y * b14.w + ra.z * b8;
                const float db0 = rbt.x * b04.x + rbt.y * b04.y + rbt.z * b04.z;
                const float db1 = rbt.x * b04.w + rbt.y * b14.x + rbt.z * b14.y;
                const float db2 = rbt.x * b14.z + rbt.y * b14.w + rbt.z * b8;
                float4 ov;
                ov.x = (m0 == 0) ? da0 : ((m0 == 1) ? da1 : da2);
                ov.y = (m0 == 0) ? da1 : ((m0 == 1) ? da2 : db0);
                ov.z = (m0 == 0) ? da2 : ((m0 == 1) ? db0 : db1);
                ov.w = (m0 == 0) ? db0 : ((m0 == 1) ? db1 : db2);
                *(float4*)(oc + (size_t)e * OUT_PER_EDGE + 4 * rem) = ov;
                rem += 32;
                if (rem >= 36) { rem -= 36; e += 1; }
            }
        }
        CP_WAIT0();
        __syncthreads();   // flip B buffers; all warps' TP done before next GEMM
    }
}

// ---------------------------------------------------------------------------
extern "C" void kernel_launch(void* const* d_in, const int* in_sizes, int n_in,
                              void* d_out, int out_size)
{
    const float* feat  = (const float*)d_in[0];
    const float* basis = (const float*)d_in[1];
    const float* W1    = (const float*)d_in[2];
    const float* b1    = (const float*)d_in[3];
    const float* g1    = (const float*)d_in[4];
    const float* W2    = (const float*)d_in[5];
    const float* b2    = (const float*)d_in[6];
    const float* g2    = (const float*)d_in[7];
    const float* W3    = (const float*)d_in[8];
    const float* b3    = (const float*)d_in[9];
    float* out = (float*)d_out;

    cudaFuncSetAttribute(k2_fused, cudaFuncAttributeMaxDynamicSharedMemorySize, SM_TOTAL);

    k0_prep<<<(R_DIM * KB + 255) / 256, 256>>>(W3);
    k2_fused<<<NCTA, 256, SM_TOTAL>>>(feat, basis, W1, b1, g1, W2, b2, g2, b3, out);
}